// round 15
// baseline (speedup 1.0000x reference)
#include <cuda_runtime.h>
#include <cuda_bf16.h>
#include <cuda_fp16.h>
#include <math.h>
#include <stdint.h>

#define D 128
#define NMAX 100000
#define EMAX 1000000
#define SECT 256
#define NBLK 391                 // ceil(NMAX/256)

#define PI_F      3.14159265358979f
#define HALFPI_F  1.57079632679490f
#define TWOPI_F   6.28318530717959f

// ---------------- scratch (static device globals; no runtime alloc) ------------
__device__ float g_acc[(size_t)NMAX * D];   // per-dst accumulated messages
__device__ int   g_cnt_i[NMAX];             // per-dst edge counts
__device__ float g_bounds[SECT];            // sorted sector boundary angles
__device__ __half2 g_UVh[SECT * D];         // sector tables, fp16 (U,V)
__device__ float g_colsum[D];               // BN stats
__device__ float g_colsq[D];
__device__ int   g_ei64;                    // 1 if edge_index is int64
__device__ unsigned g_Wpk[16 * 2048];       // W pre-split bf16 H|L pairs
__device__ int   g_bsum[NBLK];              // scan partials
__device__ int   g_boff[NBLK];
__device__ int   g_off[NMAX];               // CSR offsets
__device__ int   g_pos[NMAX];               // running positions (end = offsets+deg)
__device__ unsigned g_sm[EMAX];             // sorted: src | (sct<<20)
__device__ float2   g_sw[EMAX];             // sorted: (w0, w1)

// ---------------- K0: small zeroing + dtype detect ------------------------------
__global__ void k_zero(const int* __restrict__ w) {
    if (blockIdx.x == 0 && threadIdx.x == 0) {
        int all0 = 1;
        #pragma unroll
        for (int j = 1; j < 64; j += 2) all0 &= (w[j] == 0);
        g_ei64 = all0;
    }
    int stride = gridDim.x * blockDim.x;
    for (int i = blockIdx.x * blockDim.x + threadIdx.x; i < NMAX; i += stride)
        g_cnt_i[i] = 0;
    if (blockIdx.x == 0 && threadIdx.x < D) {
        g_colsum[threadIdx.x] = 0.f;
        g_colsq[threadIdx.x]  = 0.f;
    }
}

// ---------------- bf16 helpers --------------------------------------------------
__device__ __forceinline__ void split_bf16(float a, float& hi, float& lo) {
    hi = __bfloat162float(__float2bfloat16_rn(a));
    lo = a - hi;
}
__device__ __forceinline__ unsigned pack_bf16(float even, float odd) {
    unsigned r;
    asm("cvt.rn.bf16x2.f32 %0, %1, %2;" : "=r"(r) : "f"(odd), "f"(even));
    return r;
}

// ---------------- K1: bounds + sector tables ------------------------------------
__global__ __launch_bounds__(256) void k_sectors(const float* __restrict__ pw1,
                                                 const float* __restrict__ pw2) {
    __shared__ float raw[SECT];
    __shared__ float sb[SECT];
    __shared__ float Am[D], Bm[D];
    __shared__ float su[D], sv[D];
    int t = threadIdx.x;
    if (t < D) {
        float A = pw1[t];
        float B = pw1[D + t];
        float phi = atan2f(B, A);
        float c0 = phi + HALFPI_F; if (c0 >  PI_F) c0 -= TWOPI_F;
        float c1 = phi - HALFPI_F; if (c1 < -PI_F) c1 += TWOPI_F;
        raw[2 * t]     = c0;
        raw[2 * t + 1] = c1;
    }
    __syncthreads();
    float v = raw[t];
    int rank = 0;
    #pragma unroll 8
    for (int j = 0; j < SECT; j++) {
        float u = raw[j];
        rank += (u < v) || (u == v && j < t);
    }
    sb[rank] = v;
    if (blockIdx.x == 0) g_bounds[rank] = v;
    __syncthreads();

    int s = blockIdx.x;
    float b0 = sb[s];
    float b1 = (s < SECT - 1) ? sb[s + 1] : (sb[0] + TWOPI_F);
    float thc = 0.5f * (b0 + b1);
    float c = cosf(thc), sn = sinf(thc);
    if (t < D) {
        float A = pw1[t], B = pw1[D + t];
        bool m = fmaf(A, c, B * sn) > 0.f;
        Am[t] = m ? A : 0.f;
        Bm[t] = m ? B : 0.f;
    }
    __syncthreads();
    int k = t & (D - 1);
    bool dov = t >= D;
    float acc = 0.f;
    #pragma unroll 8
    for (int d = 0; d < D; d++) {
        float w = pw2[d * D + k];
        acc = fmaf(dov ? Bm[d] : Am[d], w, acc);
    }
    if (dov) sv[k] = acc;
    else     su[k] = acc;
    __syncthreads();
    if (t < D) g_UVh[s * D + t] = __floats2half2_rn(su[t], sv[t]);
}

// ---------------- K2b: W pre-split into packed bf16 H|L pair tiles --------------
__global__ void k_wprep(const float* __restrict__ W) {
    int idx = blockIdx.x * blockDim.x + threadIdx.x;   // 16*128*8
    if (idx < 16 * 128 * 8) {
        int kt = idx >> 10;
        int n  = (idx >> 3) & 127;
        int kp = idx & 7;
        float e = W[(size_t)(kt * 16 + 2 * kp) * D + n];
        float o = W[(size_t)(kt * 16 + 2 * kp + 1) * D + n];
        float eh, el, oh, ol;
        split_bf16(e, eh, el);
        split_bf16(o, oh, ol);
        g_Wpk[kt * 2048 + n * 16 + kp]     = pack_bf16(eh, oh);
        g_Wpk[kt * 2048 + n * 16 + 8 + kp] = pack_bf16(el, ol);
    }
}

// ---------------- K3a: per-dst counts -------------------------------------------
__global__ void k_count(const void* __restrict__ ei_raw, int E) {
    const long long* ei64 = (const long long*)ei_raw;
    const int*       ei32 = (const int*)ei_raw;
    int is64 = g_ei64;
    int stride = gridDim.x * blockDim.x;
    for (int e = blockIdx.x * blockDim.x + threadIdx.x; e < E; e += stride) {
        int dst = is64 ? (int)ei64[E + e] : ei32[E + e];
        atomicAdd(&g_cnt_i[dst], 1);
    }
}

// ---------------- K3b-d: prefix scan (block sums -> scan -> offsets) ------------
__global__ void k_scan1() {
    __shared__ int sm[256];
    int b = blockIdx.x, t = threadIdx.x;
    int d = b * 256 + t;
    int v = (d < NMAX) ? g_cnt_i[d] : 0;
    sm[t] = v;
    __syncthreads();
    for (int off = 128; off > 0; off >>= 1) {
        if (t < off) sm[t] += sm[t + off];
        __syncthreads();
    }
    if (t == 0) g_bsum[b] = sm[0];
}
__global__ void k_scan2() {
    __shared__ int sm[512];
    int t = threadIdx.x;
    sm[t] = (t < NBLK) ? g_bsum[t] : 0;
    __syncthreads();
    // Hillis-Steele inclusive scan over 512
    for (int off = 1; off < 512; off <<= 1) {
        int v = (t >= off) ? sm[t - off] : 0;
        __syncthreads();
        sm[t] += v;
        __syncthreads();
    }
    if (t < NBLK) g_boff[t] = sm[t] - g_bsum[t];   // exclusive
}
__global__ void k_scan3() {
    __shared__ int sm[256];
    int b = blockIdx.x, t = threadIdx.x;
    int d = b * 256 + t;
    int v = (d < NMAX) ? g_cnt_i[d] : 0;
    sm[t] = v;
    __syncthreads();
    for (int off = 1; off < 256; off <<= 1) {
        int u = (t >= off) ? sm[t - off] : 0;
        __syncthreads();
        sm[t] += u;
        __syncthreads();
    }
    if (d < NMAX) {
        int off = g_boff[b] + sm[t] - v;   // exclusive
        g_off[d] = off;
        g_pos[d] = off;
    }
}

// ---------------- K3e: scatter edges into CSR order -----------------------------
__global__ __launch_bounds__(256) void k_scatter(const void* __restrict__ ei_raw,
                                                 const float* __restrict__ ew, int E) {
    __shared__ float sbound[SECT];
    int t = threadIdx.x;
    sbound[t] = g_bounds[t];
    __syncthreads();
    const long long* ei64 = (const long long*)ei_raw;
    const int*       ei32 = (const int*)ei_raw;
    int is64 = g_ei64;
    int stride = gridDim.x * blockDim.x;
    for (int e = blockIdx.x * blockDim.x + t; e < E; e += stride) {
        int src, dst;
        if (is64) { src = (int)ei64[e]; dst = (int)ei64[E + e]; }
        else      { src = ei32[e];      dst = ei32[E + e]; }
        float2 wv = reinterpret_cast<const float2*>(ew)[e];
        float th = atan2f(wv.y, wv.x);
        int lo = 0, hi = SECT;
        while (lo < hi) {
            int mid = (lo + hi) >> 1;
            if (sbound[mid] <= th) lo = mid + 1; else hi = mid;
        }
        int sct = (lo == 0) ? (SECT - 1) : (lo - 1);
        int pos = atomicAdd(&g_pos[dst], 1);
        g_sm[pos] = (unsigned)src | ((unsigned)sct << 20);
        g_sw[pos] = wv;
    }
}

// ---------------- K3f: CSR edge aggregation (warp per dst, no atomics) ----------
__global__ __launch_bounds__(256) void k_edges_csr(const float* __restrict__ x, int n) {
    int lane = threadIdx.x & 31;
    int gw   = blockIdx.x * 8 + (threadIdx.x >> 5);
    int nw   = gridDim.x * 8;

    for (int d = gw; d < n; d += nw) {
        int n0 = g_off[d];
        int n1 = g_pos[d];          // end (offsets advanced by scatter)
        if (n0 == n1) continue;     // deg-0: row stays zero (never written)

        float4 acc = make_float4(0.f, 0.f, 0.f, 0.f);
        for (int base = n0; base < n1; base += 32) {
            int i = base + lane;
            unsigned m = 0; float2 wv = make_float2(0.f, 0.f);
            if (i < n1) { m = g_sm[i]; wv = g_sw[i]; }
            int cnt = n1 - base; if (cnt > 32) cnt = 32;
            for (int j = 0; j < cnt; j++) {
                unsigned m_  = __shfl_sync(0xffffffffu, m, j);
                float a0_ = __shfl_sync(0xffffffffu, wv.x, j);
                float a1_ = __shfl_sync(0xffffffffu, wv.y, j);
                int s_  = (int)(m_ & 0xFFFFFu);
                int sc_ = (int)(m_ >> 20);

                float4 xj = __ldg(reinterpret_cast<const float4*>(x + (size_t)s_ * D) + lane);
                uint4 uvr = __ldg(reinterpret_cast<const uint4*>(g_UVh + (size_t)sc_ * D) + lane);
                float2 p0 = __half22float2(*reinterpret_cast<__half2*>(&uvr.x));
                float2 p1 = __half22float2(*reinterpret_cast<__half2*>(&uvr.y));
                float2 p2 = __half22float2(*reinterpret_cast<__half2*>(&uvr.z));
                float2 p3 = __half22float2(*reinterpret_cast<__half2*>(&uvr.w));

                acc.x = fmaf(xj.x, fmaf(a0_, p0.x, fmaf(a1_, p0.y, 1.f)), acc.x);
                acc.y = fmaf(xj.y, fmaf(a0_, p1.x, fmaf(a1_, p1.y, 1.f)), acc.y);
                acc.z = fmaf(xj.z, fmaf(a0_, p2.x, fmaf(a1_, p2.y, 1.f)), acc.z);
                acc.w = fmaf(xj.w, fmaf(a0_, p3.x, fmaf(a1_, p3.y, 1.f)), acc.w);
            }
        }
        *(reinterpret_cast<float4*>(g_acc + (size_t)d * D) + lane) = acc;
    }
}

// ---------------- mma / ldmatrix helpers ----------------------------------------
__device__ __forceinline__ void mma_bf16(float* d, unsigned a0, unsigned a1,
                                         unsigned a2, unsigned a3,
                                         unsigned b0, unsigned b1) {
    asm volatile(
        "mma.sync.aligned.m16n8k16.row.col.f32.bf16.bf16.f32 "
        "{%0,%1,%2,%3}, {%4,%5,%6,%7}, {%8,%9}, {%0,%1,%2,%3};\n"
        : "+f"(d[0]), "+f"(d[1]), "+f"(d[2]), "+f"(d[3])
        : "r"(a0), "r"(a1), "r"(a2), "r"(a3), "r"(b0), "r"(b1));
}

__device__ __forceinline__ void ldsm_x4(unsigned& r0, unsigned& r1,
                                        unsigned& r2, unsigned& r3, unsigned addr) {
    asm volatile("ldmatrix.sync.aligned.m8n8.x4.shared.b16 {%0,%1,%2,%3}, [%4];"
                 : "=r"(r0), "=r"(r1), "=r"(r2), "=r"(r3) : "r"(addr));
}

// ---------------- K4: tensor-core GEMM, bf16 3-pass, double-buffered ------------
#define PITCHW 20
#define BUFW   (128 * PITCHW)
__global__ __launch_bounds__(256, 2) void k_gemm(const float* __restrict__ x,
                                                 const float* __restrict__ bias,
                                                 float* __restrict__ out, int N) {
    __shared__ unsigned sA[2 * BUFW];
    __shared__ unsigned sW[2 * BUFW];
    __shared__ float inv_s[128];
    __shared__ float scol[128], scolq[128];

    int tid = threadIdx.x;
    int row0 = blockIdx.x * 128;
    if (tid < 128) {
        int r = row0 + tid;
        inv_s[tid] = (r < N) ? (1.f / fmaxf((float)g_cnt_i[r], 1.f)) : 0.f;
        scol[tid] = 0.f; scolq[tid] = 0.f;
    }

    int lane  = tid & 31;
    int warp  = tid >> 5;
    int warpM = warp >> 2;
    int warpN = warp & 3;
    int grp   = lane >> 2;
    int th4   = lane & 3;

    unsigned sA_base = (unsigned)__cvta_generic_to_shared(sA);
    unsigned sW_base = (unsigned)__cvta_generic_to_shared(sW);
    unsigned aAddr = sA_base + (unsigned)((warpM * 64 + (lane & 15)) * 80 + (lane >> 4) * 16);
    int quad = lane >> 3;
    unsigned bAddr = sW_base + (unsigned)((warpN * 32 + ((quad >> 1) * 8) + (lane & 7)) * 80
                                          + (quad & 1) * 16);

    float c[4][4][4];
    #pragma unroll
    for (int mi = 0; mi < 4; mi++)
        #pragma unroll
        for (int ni = 0; ni < 4; ni++)
            #pragma unroll
            for (int j = 0; j < 4; j++) c[mi][ni][j] = 0.f;

    int a_m0 = tid >> 2, a_ch = tid & 3;
    int w_row = tid >> 1, w_half = tid & 1;

    __syncthreads();

    float4 av[2]; uint4 wq0, wq1;

    #define LOAD_TILE(kt)                                                             \
    {                                                                                 \
        _Pragma("unroll")                                                             \
        for (int u = 0; u < 2; u++) {                                                 \
            int m = a_m0 + u * 64;                                                    \
            int r = row0 + m;                                                         \
            av[u] = make_float4(0.f, 0.f, 0.f, 0.f);                                  \
            if (r < N) {                                                              \
                if ((kt) < 8) {                                                       \
                    av[u] = *reinterpret_cast<const float4*>(x + (size_t)r * D + (kt) * 16 + a_ch * 4); \
                } else {                                                              \
                    float iv = inv_s[m];                                              \
                    av[u] = *reinterpret_cast<const float4*>(g_acc + (size_t)r * D + ((kt) - 8) * 16 + a_ch * 4); \
                    av[u].x *= iv; av[u].y *= iv; av[u].z *= iv; av[u].w *= iv;       \
                }                                                                     \
            }                                                                         \
        }                                                                             \
        const unsigned* wsrc = g_Wpk + (kt) * 2048 + w_row * 16 + w_half * 8;         \
        wq0 = *reinterpret_cast<const uint4*>(wsrc);                                  \
        wq1 = *reinterpret_cast<const uint4*>(wsrc + 4);                              \
    }

    #define STAGE_TILE(buf)                                                           \
    {                                                                                 \
        unsigned* dA = sA + (buf) * BUFW;                                             \
        unsigned* dW = sW + (buf) * BUFW;                                             \
        _Pragma("unroll")                                                             \
        for (int u = 0; u < 2; u++) {                                                 \
            int m = a_m0 + u * 64;                                                    \
            float h0, l0, h1, l1, h2, l2, h3, l3;                                     \
            split_bf16(av[u].x, h0, l0);                                              \
            split_bf16(av[u].y, h1, l1);                                              \
            split_bf16(av[u].z, h2, l2);                                              \
            split_bf16(av[u].w, h3, l3);                                              \
            int base = m * PITCHW + a_ch * 2;                                         \
            *reinterpret_cast<uint2*>(&dA[base])     = make_uint2(pack_bf16(h0, h1), pack_bf16(h2, h3)); \
            *reinterpret_cast<uint2*>(&dA[base + 8]) = make_uint2(pack_bf16(l0, l1), pack_bf16(l2, l3)); \
        }                                                                             \
        unsigned* wdst = dW + w_row * PITCHW + w_half * 8;                            \
        *reinterpret_cast<uint4*>(wdst)     = wq0;                                    \
        *reinterpret_cast<uint4*>(wdst + 4) = wq1;                                    \
    }

    LOAD_TILE(0)
    STAGE_TILE(0)
    __syncthreads();

    for (int kt = 0; kt < 16; kt++) {
        if (kt < 15) LOAD_TILE(kt + 1)

        unsigned bufOff = (unsigned)((kt & 1) * BUFW * 4);
        unsigned bH[4][2], bL[4][2];
        #pragma unroll
        for (int p = 0; p < 2; p++) {
            unsigned off = bufOff + (unsigned)(p * 16 * 80);
            ldsm_x4(bH[2*p][0], bH[2*p][1], bH[2*p+1][0], bH[2*p+1][1], bAddr + off);
            ldsm_x4(bL[2*p][0], bL[2*p][1], bL[2*p+1][0], bL[2*p+1][1], bAddr + off + 32);
        }
        #pragma unroll
        for (int mi = 0; mi < 4; mi++) {
            unsigned off = bufOff + (unsigned)(mi * 16 * 80);
            unsigned aH0, aH1, aH2, aH3, aL0, aL1, aL2, aL3;
            ldsm_x4(aH0, aH1, aH2, aH3, aAddr + off);
            ldsm_x4(aL0, aL1, aL2, aL3, aAddr + off + 32);
            #pragma unroll
            for (int ni = 0; ni < 4; ni++) {
                mma_bf16(c[mi][ni], aH0, aH1, aH2, aH3, bH[ni][0], bH[ni][1]);
                mma_bf16(c[mi][ni], aH0, aH1, aH2, aH3, bL[ni][0], bL[ni][1]);
                mma_bf16(c[mi][ni], aL0, aL1, aL2, aL3, bH[ni][0], bH[ni][1]);
            }
        }

        if (kt < 15) STAGE_TILE((kt + 1) & 1)
        __syncthreads();
    }
    #undef LOAD_TILE
    #undef STAGE_TILE

    // ---- epilogue: bias + store + BN stats ----
    float ss[4][2], qq[4][2];
    #pragma unroll
    for (int ni = 0; ni < 4; ni++) { ss[ni][0]=ss[ni][1]=qq[ni][0]=qq[ni][1]=0.f; }

    #pragma unroll
    for (int ni = 0; ni < 4; ni++) {
        int col = warpN * 32 + ni * 8 + 2 * th4;
        float b0 = __ldg(bias + col), b1 = __ldg(bias + col + 1);
        #pragma unroll
        for (int mi = 0; mi < 4; mi++) {
            int rlo = row0 + warpM * 64 + mi * 16 + grp;
            if (rlo < N) {
                float v0 = c[mi][ni][0] + b0;
                float v1 = c[mi][ni][1] + b1;
                *reinterpret_cast<float2*>(out + (size_t)rlo * D + col) = make_float2(v0, v1);
                ss[ni][0] += v0; qq[ni][0] += v0 * v0;
                ss[ni][1] += v1; qq[ni][1] += v1 * v1;
            }
            int rhi = rlo + 8;
            if (rhi < N) {
                float v2 = c[mi][ni][2] + b0;
                float v3 = c[mi][ni][3] + b1;
                *reinterpret_cast<float2*>(out + (size_t)rhi * D + col) = make_float2(v2, v3);
                ss[ni][0] += v2; qq[ni][0] += v2 * v2;
                ss[ni][1] += v3; qq[ni][1] += v3 * v3;
            }
        }
    }
    #pragma unroll
    for (int ni = 0; ni < 4; ni++)
        #pragma unroll
        for (int j = 0; j < 2; j++) {
            float s = ss[ni][j], q = qq[ni][j];
            #pragma unroll
            for (int off = 4; off < 32; off <<= 1) {
                s += __shfl_xor_sync(0xffffffffu, s, off);
                q += __shfl_xor_sync(0xffffffffu, q, off);
            }
            if (lane < 4) {
                int col = warpN * 32 + ni * 8 + 2 * lane + j;
                atomicAdd(&scol[col],  s);
                atomicAdd(&scolq[col], q);
            }
        }
    __syncthreads();
    if (tid < D) {
        atomicAdd(&g_colsum[tid], scol[tid]);
        atomicAdd(&g_colsq[tid],  scolq[tid]);
    }
}

// ---------------- K5: BN finalize + relu + residual -----------------------------
__global__ void k_bn(const float* __restrict__ x, const float* __restrict__ gamma,
                     const float* __restrict__ beta, float* __restrict__ out, int N) {
    __shared__ float ssc[D], ssh[D];
    int t = threadIdx.x;
    if (t < D) {
        float invN = 1.f / (float)N;
        float mean = g_colsum[t] * invN;
        float var  = g_colsq[t] * invN - mean * mean;
        float sc = gamma[t] * rsqrtf(var + 1e-5f);
        ssc[t] = sc;
        ssh[t] = beta[t] - mean * sc;
    }
    __syncthreads();
    int i = blockIdx.x * blockDim.x + t;
    int tot = N * (D / 4);
    if (i < tot) {
        int c = (i & 31) * 4;
        float4 o  = reinterpret_cast<float4*>(out)[i];
        float4 xr = reinterpret_cast<const float4*>(x)[i];
        o.x = fmaxf(fmaf(o.x, ssc[c + 0], ssh[c + 0]), 0.f) + xr.x;
        o.y = fmaxf(fmaf(o.y, ssc[c + 1], ssh[c + 1]), 0.f) + xr.y;
        o.z = fmaxf(fmaf(o.z, ssc[c + 2], ssh[c + 2]), 0.f) + xr.z;
        o.w = fmaxf(fmaf(o.w, ssc[c + 3], ssh[c + 3]), 0.f) + xr.w;
        reinterpret_cast<float4*>(out)[i] = o;
    }
}

// ---------------- launch --------------------------------------------------------
extern "C" void kernel_launch(void* const* d_in, const int* in_sizes, int n_in,
                              void* d_out, int out_size) {
    const float* x     = (const float*)d_in[0];
    const void*  ei    = d_in[1];
    const float* ew    = (const float*)d_in[2];
    const float* pw1   = (const float*)d_in[3];
    const float* pw2   = (const float*)d_in[4];
    const float* sw    = (const float*)d_in[5];
    const float* sb    = (const float*)d_in[6];
    const float* gamma = (const float*)d_in[7];
    const float* beta  = (const float*)d_in[8];
    float* out = (float*)d_out;

    int N = in_sizes[0] / D;
    int E = in_sizes[1] / 2;

    k_zero<<<128, 256>>>((const int*)ei);
    k_count<<<512, 256>>>(ei, E);
    k_sectors<<<SECT, 256>>>(pw1, pw2);
    k_wprep<<<64, 256>>>(sw);
    k_scan1<<<NBLK, 256>>>();
    k_scan2<<<1, 512>>>();
    k_scan3<<<NBLK, 256>>>();
    k_scatter<<<1024, 256>>>(ei, ew, E);
    k_edges_csr<<<2048, 256>>>(x, N);
    k_gemm<<<(N + 127) / 128, 256>>>(x, sb, out, N);
    k_bn<<<(N * (D / 4) + 255) / 256, 256>>>(x, gamma, beta, out, N);
}

// round 16
// speedup vs baseline: 1.0139x; 1.0139x over previous
#include <cuda_runtime.h>
#include <cuda_bf16.h>
#include <cuda_fp16.h>
#include <math.h>
#include <stdint.h>

#define D 128
#define NMAX 100000
#define SECT 256

#define PI_F      3.14159265358979f
#define HALFPI_F  1.57079632679490f
#define TWOPI_F   6.28318530717959f

// ---------------- scratch (static device globals; no runtime alloc) ------------
__device__ float g_acc[(size_t)NMAX * D];   // 51.2 MB scatter accumulator
__device__ __half g_xh[(size_t)NMAX * D];   // fp16 copy of x for the gather
__device__ float g_cnt[NMAX];               // per-dst edge counts
__device__ float g_bounds[SECT];            // sorted sector boundary angles
__device__ __half2 g_UVh[SECT * D];         // sector tables, fp16 (U,V) pairs
__device__ float g_colsum[D];               // BN stats
__device__ float g_colsq[D];
__device__ int   g_ei64;                    // 1 if edge_index is int64
__device__ unsigned g_Wpk[16 * 2048];       // W pre-split bf16 H|L pairs per k-tile

// ---------------- K0: zero scratch + x->fp16 + dtype detect ---------------------
__global__ void k_zero(const int* __restrict__ w, const float* __restrict__ x, int n) {
    if (blockIdx.x == 0 && threadIdx.x == 0) {
        int all0 = 1;
        #pragma unroll
        for (int j = 1; j < 64; j += 2) all0 &= (w[j] == 0);
        g_ei64 = all0;
    }
    int nd4 = n * (D / 4);
    float4 z = make_float4(0.f, 0.f, 0.f, 0.f);
    int stride = gridDim.x * blockDim.x;
    for (int i = blockIdx.x * blockDim.x + threadIdx.x; i < nd4; i += stride) {
        reinterpret_cast<float4*>(g_acc)[i] = z;
        float4 xv = reinterpret_cast<const float4*>(x)[i];
        __half2 h0 = __floats2half2_rn(xv.x, xv.y);
        __half2 h1 = __floats2half2_rn(xv.z, xv.w);
        unsigned lo = *reinterpret_cast<unsigned*>(&h0);
        unsigned hi = *reinterpret_cast<unsigned*>(&h1);
        reinterpret_cast<uint2*>(g_xh)[i] = make_uint2(lo, hi);
    }
    for (int i = blockIdx.x * blockDim.x + threadIdx.x; i < n; i += stride)
        g_cnt[i] = 0.f;
    if (blockIdx.x == 0 && threadIdx.x < D) {
        g_colsum[threadIdx.x] = 0.f;
        g_colsq[threadIdx.x]  = 0.f;
    }
}

// ---------------- bf16 helpers --------------------------------------------------
__device__ __forceinline__ void split_bf16(float a, float& hi, float& lo) {
    hi = __bfloat162float(__float2bfloat16_rn(a));
    lo = a - hi;
}
__device__ __forceinline__ unsigned pack_bf16(float even, float odd) {
    unsigned r;
    asm("cvt.rn.bf16x2.f32 %0, %1, %2;" : "=r"(r) : "f"(odd), "f"(even));
    return r;
}

// ---------------- K1: bounds + sector tables (merged; 256 blocks x 256 thr) -----
__global__ __launch_bounds__(256) void k_sectors(const float* __restrict__ pw1,
                                                 const float* __restrict__ pw2) {
    __shared__ float raw[SECT];
    __shared__ float sb[SECT];
    __shared__ float Am[D], Bm[D];
    __shared__ float su[D], sv[D];
    int t = threadIdx.x;
    if (t < D) {
        float A = pw1[t];
        float B = pw1[D + t];
        float phi = atan2f(B, A);
        float c0 = phi + HALFPI_F; if (c0 >  PI_F) c0 -= TWOPI_F;
        float c1 = phi - HALFPI_F; if (c1 < -PI_F) c1 += TWOPI_F;
        raw[2 * t]     = c0;
        raw[2 * t + 1] = c1;
    }
    __syncthreads();
    float v = raw[t];
    int rank = 0;
    #pragma unroll 8
    for (int j = 0; j < SECT; j++) {
        float u = raw[j];
        rank += (u < v) || (u == v && j < t);
    }
    sb[rank] = v;
    if (blockIdx.x == 0) g_bounds[rank] = v;
    __syncthreads();

    int s = blockIdx.x;
    float b0 = sb[s];
    float b1 = (s < SECT - 1) ? sb[s + 1] : (sb[0] + TWOPI_F);
    float thc = 0.5f * (b0 + b1);
    float c = cosf(thc), sn = sinf(thc);
    if (t < D) {
        float A = pw1[t], B = pw1[D + t];
        bool m = fmaf(A, c, B * sn) > 0.f;
        Am[t] = m ? A : 0.f;
        Bm[t] = m ? B : 0.f;
    }
    __syncthreads();
    int k = t & (D - 1);
    bool dov = t >= D;
    float acc = 0.f;
    #pragma unroll 8
    for (int d = 0; d < D; d++) {
        float w = pw2[d * D + k];
        acc = fmaf(dov ? Bm[d] : Am[d], w, acc);
    }
    if (dov) sv[k] = acc;
    else     su[k] = acc;
    __syncthreads();
    if (t < D) g_UVh[s * D + t] = __floats2half2_rn(su[t], sv[t]);
}

// ---------------- K2b: W pre-split into packed bf16 H|L pair tiles --------------
__global__ void k_wprep(const float* __restrict__ W) {
    int idx = blockIdx.x * blockDim.x + threadIdx.x;   // 16*128*8
    if (idx < 16 * 128 * 8) {
        int kt = idx >> 10;
        int n  = (idx >> 3) & 127;
        int kp = idx & 7;
        float e = W[(size_t)(kt * 16 + 2 * kp) * D + n];
        float o = W[(size_t)(kt * 16 + 2 * kp + 1) * D + n];
        float eh, el, oh, ol;
        split_bf16(e, eh, el);
        split_bf16(o, oh, ol);
        g_Wpk[kt * 2048 + n * 16 + kp]     = pack_bf16(eh, oh);
        g_Wpk[kt * 2048 + n * 16 + 8 + kp] = pack_bf16(el, ol);
    }
}

// ---------------- K3: edges — packed metadata, fp16 gather ----------------------
__global__ __launch_bounds__(256) void k_edges(const void* __restrict__ ei_raw,
                                               const float* __restrict__ ew, int E) {
    __shared__ float sbound[SECT];
    int t = threadIdx.x;
    sbound[t] = g_bounds[t];
    __syncthreads();
    const long long* ei64 = (const long long*)ei_raw;
    const int*       ei32 = (const int*)ei_raw;
    int is64 = g_ei64;
    int lane = t & 31;
    int wid  = blockIdx.x * 8 + (t >> 5);
    int stride = gridDim.x * 8 * 32;

    for (int e0 = wid * 32; e0 < E; e0 += stride) {
        int e = e0 + lane;
        unsigned m = 0, whp = 0;
        int dst = 0;
        if (e < E) {
            int src;
            if (is64) { src = (int)ei64[e]; dst = (int)ei64[E + e]; }
            else      { src = ei32[e];      dst = ei32[E + e]; }
            float2 wv = reinterpret_cast<const float2*>(ew)[e];
            float th = atan2f(wv.y, wv.x);
            int lo = 0, hi = SECT;
            while (lo < hi) {
                int mid = (lo + hi) >> 1;
                if (sbound[mid] <= th) lo = mid + 1; else hi = mid;
            }
            int sct = (lo == 0) ? (SECT - 1) : (lo - 1);
            m = (unsigned)src | ((unsigned)sct << 20);
            __half2 wh = __floats2half2_rn(wv.x, wv.y);
            whp = *reinterpret_cast<unsigned*>(&wh);
            atomicAdd(&g_cnt[dst], 1.f);
        }

        #define EDGE_BODY(i)                                                          \
        {                                                                             \
            unsigned m_  = __shfl_sync(0xffffffffu, m, (i));                          \
            int   dd_    = __shfl_sync(0xffffffffu, dst, (i));                        \
            unsigned wh_ = __shfl_sync(0xffffffffu, whp, (i));                        \
            int s_  = (int)(m_ & 0xFFFFFu);                                           \
            int sc_ = (int)(m_ >> 20);                                                \
            float2 wf = __half22float2(*reinterpret_cast<__half2*>(&wh_));            \
            uint2 xr = __ldg(reinterpret_cast<const uint2*>(g_xh + (size_t)s_ * D) + lane); \
            float2 x01 = __half22float2(*reinterpret_cast<__half2*>(&xr.x));          \
            float2 x23 = __half22float2(*reinterpret_cast<__half2*>(&xr.y));          \
            uint4 uvr = __ldg(reinterpret_cast<const uint4*>(g_UVh + (size_t)sc_ * D) + lane); \
            float2 p0 = __half22float2(*reinterpret_cast<__half2*>(&uvr.x));          \
            float2 p1 = __half22float2(*reinterpret_cast<__half2*>(&uvr.y));          \
            float2 p2 = __half22float2(*reinterpret_cast<__half2*>(&uvr.z));          \
            float2 p3 = __half22float2(*reinterpret_cast<__half2*>(&uvr.w));          \
            float4 msg;                                                               \
            msg.x = x01.x * fmaf(wf.x, p0.x, fmaf(wf.y, p0.y, 1.f));                  \
            msg.y = x01.y * fmaf(wf.x, p1.x, fmaf(wf.y, p1.y, 1.f));                  \
            msg.z = x23.x * fmaf(wf.x, p2.x, fmaf(wf.y, p2.y, 1.f));                  \
            msg.w = x23.y * fmaf(wf.x, p3.x, fmaf(wf.y, p3.y, 1.f));                  \
            float* p = g_acc + (size_t)dd_ * D + lane * 4;                            \
            asm volatile("red.global.add.v4.f32 [%0], {%1, %2, %3, %4};"              \
                         :: "l"(p), "f"(msg.x), "f"(msg.y), "f"(msg.z), "f"(msg.w) : "memory"); \
        }

        int cnt = E - e0; if (cnt > 32) cnt = 32;
        if (cnt == 32) {
            #pragma unroll 4
            for (int i = 0; i < 32; i++) EDGE_BODY(i)
        } else {
            for (int i = 0; i < cnt; i++) EDGE_BODY(i)
        }
        #undef EDGE_BODY
    }
}

// ---------------- mma / ldmatrix helpers ----------------------------------------
__device__ __forceinline__ void mma_bf16(float* d, unsigned a0, unsigned a1,
                                         unsigned a2, unsigned a3,
                                         unsigned b0, unsigned b1) {
    asm volatile(
        "mma.sync.aligned.m16n8k16.row.col.f32.bf16.bf16.f32 "
        "{%0,%1,%2,%3}, {%4,%5,%6,%7}, {%8,%9}, {%0,%1,%2,%3};\n"
        : "+f"(d[0]), "+f"(d[1]), "+f"(d[2]), "+f"(d[3])
        : "r"(a0), "r"(a1), "r"(a2), "r"(a3), "r"(b0), "r"(b1));
}

__device__ __forceinline__ void ldsm_x4(unsigned& r0, unsigned& r1,
                                        unsigned& r2, unsigned& r3, unsigned addr) {
    asm volatile("ldmatrix.sync.aligned.m8n8.x4.shared.b16 {%0,%1,%2,%3}, [%4];"
                 : "=r"(r0), "=r"(r1), "=r"(r2), "=r"(r3) : "r"(addr));
}

// ---------------- K4: tensor-core GEMM, bf16 3-pass, double-buffered ------------
#define PITCHW 20
#define BUFW   (128 * PITCHW)
__global__ __launch_bounds__(256, 2) void k_gemm(const float* __restrict__ x,
                                                 const float* __restrict__ bias,
                                                 float* __restrict__ out, int N) {
    __shared__ unsigned sA[2 * BUFW];
    __shared__ unsigned sW[2 * BUFW];
    __shared__ float inv_s[128];
    __shared__ float scol[128], scolq[128];

    int tid = threadIdx.x;
    int row0 = blockIdx.x * 128;
    if (tid < 128) {
        int r = row0 + tid;
        inv_s[tid] = (r < N) ? (1.f / fmaxf(g_cnt[r], 1.f)) : 0.f;
        scol[tid] = 0.f; scolq[tid] = 0.f;
    }

    int lane  = tid & 31;
    int warp  = tid >> 5;
    int warpM = warp >> 2;
    int warpN = warp & 3;
    int grp   = lane >> 2;
    int th4   = lane & 3;

    unsigned sA_base = (unsigned)__cvta_generic_to_shared(sA);
    unsigned sW_base = (unsigned)__cvta_generic_to_shared(sW);
    unsigned aAddr = sA_base + (unsigned)((warpM * 64 + (lane & 15)) * 80 + (lane >> 4) * 16);
    int quad = lane >> 3;
    unsigned bAddr = sW_base + (unsigned)((warpN * 32 + ((quad >> 1) * 8) + (lane & 7)) * 80
                                          + (quad & 1) * 16);

    float c[4][4][4];
    #pragma unroll
    for (int mi = 0; mi < 4; mi++)
        #pragma unroll
        for (int ni = 0; ni < 4; ni++)
            #pragma unroll
            for (int j = 0; j < 4; j++) c[mi][ni][j] = 0.f;

    int a_m0 = tid >> 2, a_ch = tid & 3;
    int w_row = tid >> 1, w_half = tid & 1;

    __syncthreads();

    float4 av[2]; uint4 wq0, wq1;

    #define LOAD_TILE(kt)                                                             \
    {                                                                                 \
        _Pragma("unroll")                                                             \
        for (int u = 0; u < 2; u++) {                                                 \
            int m = a_m0 + u * 64;                                                    \
            int r = row0 + m;                                                         \
            av[u] = make_float4(0.f, 0.f, 0.f, 0.f);                                  \
            if (r < N) {                                                              \
                if ((kt) < 8) {                                                       \
                    av[u] = *reinterpret_cast<const float4*>(x + (size_t)r * D + (kt) * 16 + a_ch * 4); \
                } else {                                                              \
                    float iv = inv_s[m];                                              \
                    av[u] = *reinterpret_cast<const float4*>(g_acc + (size_t)r * D + ((kt) - 8) * 16 + a_ch * 4); \
                    av[u].x *= iv; av[u].y *= iv; av[u].z *= iv; av[u].w *= iv;       \
                }                                                                     \
            }                                                                         \
        }                                                                             \
        const unsigned* wsrc = g_Wpk + (kt) * 2048 + w_row * 16 + w_half * 8;         \
        wq0 = *reinterpret_cast<const uint4*>(wsrc);                                  \
        wq1 = *reinterpret_cast<const uint4*>(wsrc + 4);                              \
    }

    #define STAGE_TILE(buf)                                                           \
    {                                                                                 \
        unsigned* dA = sA + (buf) * BUFW;                                             \
        unsigned* dW = sW + (buf) * BUFW;                                             \
        _Pragma("unroll")                                                             \
        for (int u = 0; u < 2; u++) {                                                 \
            int m = a_m0 + u * 64;                                                    \
            float h0, l0, h1, l1, h2, l2, h3, l3;                                     \
            split_bf16(av[u].x, h0, l0);                                              \
            split_bf16(av[u].y, h1, l1);                                              \
            split_bf16(av[u].z, h2, l2);                                              \
            split_bf16(av[u].w, h3, l3);                                              \
            int base = m * PITCHW + a_ch * 2;                                         \
            *reinterpret_cast<uint2*>(&dA[base])     = make_uint2(pack_bf16(h0, h1), pack_bf16(h2, h3)); \
            *reinterpret_cast<uint2*>(&dA[base + 8]) = make_uint2(pack_bf16(l0, l1), pack_bf16(l2, l3)); \
        }                                                                             \
        unsigned* wdst = dW + w_row * PITCHW + w_half * 8;                            \
        *reinterpret_cast<uint4*>(wdst)     = wq0;                                    \
        *reinterpret_cast<uint4*>(wdst + 4) = wq1;                                    \
    }

    LOAD_TILE(0)
    STAGE_TILE(0)
    __syncthreads();

    for (int kt = 0; kt < 16; kt++) {
        if (kt < 15) LOAD_TILE(kt + 1)

        unsigned bufOff = (unsigned)((kt & 1) * BUFW * 4);
        unsigned bH[4][2], bL[4][2];
        #pragma unroll
        for (int p = 0; p < 2; p++) {
            unsigned off = bufOff + (unsigned)(p * 16 * 80);
            ldsm_x4(bH[2*p][0], bH[2*p][1], bH[2*p+1][0], bH[2*p+1][1], bAddr + off);
            ldsm_x4(bL[2*p][0], bL[2*p][1], bL[2*p+1][0], bL[2*p+1][1], bAddr + off + 32);
        }
        #pragma unroll
        for (int mi = 0; mi < 4; mi++) {
            unsigned off = bufOff + (unsigned)(mi * 16 * 80);
            unsigned aH0, aH1, aH2, aH3, aL0, aL1, aL2, aL3;
            ldsm_x4(aH0, aH1, aH2, aH3, aAddr + off);
            ldsm_x4(aL0, aL1, aL2, aL3, aAddr + off + 32);
            #pragma unroll
            for (int ni = 0; ni < 4; ni++) {
                mma_bf16(c[mi][ni], aH0, aH1, aH2, aH3, bH[ni][0], bH[ni][1]);
                mma_bf16(c[mi][ni], aH0, aH1, aH2, aH3, bL[ni][0], bL[ni][1]);
                mma_bf16(c[mi][ni], aL0, aL1, aL2, aL3, bH[ni][0], bH[ni][1]);
            }
        }

        if (kt < 15) STAGE_TILE((kt + 1) & 1)
        __syncthreads();
    }
    #undef LOAD_TILE
    #undef STAGE_TILE

    // ---- epilogue: bias + store + BN stats ----
    float ss[4][2], qq[4][2];
    #pragma unroll
    for (int ni = 0; ni < 4; ni++) { ss[ni][0]=ss[ni][1]=qq[ni][0]=qq[ni][1]=0.f; }

    #pragma unroll
    for (int ni = 0; ni < 4; ni++) {
        int col = warpN * 32 + ni * 8 + 2 * th4;
        float b0 = __ldg(bias + col), b1 = __ldg(bias + col + 1);
        #pragma unroll
        for (int mi = 0; mi < 4; mi++) {
            int rlo = row0 + warpM * 64 + mi * 16 + grp;
            if (rlo < N) {
                float v0 = c[mi][ni][0] + b0;
                float v1 = c[mi][ni][1] + b1;
                *reinterpret_cast<float2*>(out + (size_t)rlo * D + col) = make_float2(v0, v1);
                ss[ni][0] += v0; qq[ni][0] += v0 * v0;
                ss[ni][1] += v1; qq[ni][1] += v1 * v1;
            }
            int rhi = rlo + 8;
            if (rhi < N) {
                float v2 = c[mi][ni][2] + b0;
                float v3 = c[mi][ni][3] + b1;
                *reinterpret_cast<float2*>(out + (size_t)rhi * D + col) = make_float2(v2, v3);
                ss[ni][0] += v2; qq[ni][0] += v2 * v2;
                ss[ni][1] += v3; qq[ni][1] += v3 * v3;
            }
        }
    }
    #pragma unroll
    for (int ni = 0; ni < 4; ni++)
        #pragma unroll
        for (int j = 0; j < 2; j++) {
            float s = ss[ni][j], q = qq[ni][j];
            #pragma unroll
            for (int off = 4; off < 32; off <<= 1) {
                s += __shfl_xor_sync(0xffffffffu, s, off);
                q += __shfl_xor_sync(0xffffffffu, q, off);
            }
            if (lane < 4) {
                int col = warpN * 32 + ni * 8 + 2 * lane + j;
                atomicAdd(&scol[col],  s);
                atomicAdd(&scolq[col], q);
            }
        }
    __syncthreads();
    if (tid < D) {
        atomicAdd(&g_colsum[tid], scol[tid]);
        atomicAdd(&g_colsq[tid],  scolq[tid]);
    }
}

// ---------------- K5: BN finalize + relu + residual -----------------------------
__global__ void k_bn(const float* __restrict__ x, const float* __restrict__ gamma,
                     const float* __restrict__ beta, float* __restrict__ out, int N) {
    __shared__ float ssc[D], ssh[D];
    int t = threadIdx.x;
    if (t < D) {
        float invN = 1.f / (float)N;
        float mean = g_colsum[t] * invN;
        float var  = g_colsq[t] * invN - mean * mean;
        float sc = gamma[t] * rsqrtf(var + 1e-5f);
        ssc[t] = sc;
        ssh[t] = beta[t] - mean * sc;
    }
    __syncthreads();
    int i = blockIdx.x * blockDim.x + t;
    int tot = N * (D / 4);
    if (i < tot) {
        int c = (i & 31) * 4;
        float4 o  = reinterpret_cast<float4*>(out)[i];
        float4 xr = reinterpret_cast<const float4*>(x)[i];
        o.x = fmaxf(fmaf(o.x, ssc[c + 0], ssh[c + 0]), 0.f) + xr.x;
        o.y = fmaxf(fmaf(o.y, ssc[c + 1], ssh[c + 1]), 0.f) + xr.y;
        o.z = fmaxf(fmaf(o.z, ssc[c + 2], ssh[c + 2]), 0.f) + xr.z;
        o.w = fmaxf(fmaf(o.w, ssc[c + 3], ssh[c + 3]), 0.f) + xr.w;
        reinterpret_cast<float4*>(out)[i] = o;
    }
}

// ---------------- launch --------------------------------------------------------
extern "C" void kernel_launch(void* const* d_in, const int* in_sizes, int n_in,
                              void* d_out, int out_size) {
    const float* x     = (const float*)d_in[0];
    const void*  ei    = d_in[1];
    const float* ew    = (const float*)d_in[2];
    const float* pw1   = (const float*)d_in[3];
    const float* pw2   = (const float*)d_in[4];
    const float* sw    = (const float*)d_in[5];
    const float* sb    = (const float*)d_in[6];
    const float* gamma = (const float*)d_in[7];
    const float* beta  = (const float*)d_in[8];
    float* out = (float*)d_out;

    int N = in_sizes[0] / D;
    int E = in_sizes[1] / 2;

    k_zero<<<4096, 256>>>((const int*)ei, x, N);
    k_sectors<<<SECT, 256>>>(pw1, pw2);
    k_wprep<<<64, 256>>>(sw);
    k_edges<<<4096, 256>>>(ei, ew, E);
    k_gemm<<<(N + 127) / 128, 256>>>(x, sb, out, N);
    k_bn<<<(N * (D / 4) + 255) / 256, 256>>>(x, gamma, beta, out, N);
}